// round 1
// baseline (speedup 1.0000x reference)
#include <cuda_runtime.h>
#include <cuda_fp16.h>
#include <cstdint>

#define HID   512
#define DHID  2048
#define NBAT  32
#define NSEQ  2048
#define NROWS (NSEQ*NBAT)   // 65536

// ---- main kernel tiling ----
#define TM   128            // rows per CTA
#define NCH  64             // n-chunk width
#define LDA  520            // A smem stride (halfs), pad 8 -> conflict-free ldmatrix
#define LDB  520            // B smem stride (halfs)

#define AS_BYTES (TM*LDA*2)             // 133120
#define BS_OFF   (AS_BYTES)
#define BS_BYTES (64*LDB*2)             // 66560
#define HP_OFF   (BS_OFF+BS_BYTES)      // 199680
#define HP_BYTES (NBAT*65*4)            // 8320
#define VS_OFF   (HP_OFF+HP_BYTES)      // 208000
#define RS_OFF   (VS_OFF+256)           // 208256
#define SMEM_TOTAL (RS_OFF + TM*4)      // 208768

__device__ float  g_hp[NBAT*HID];
__device__ __half g_We[HID*HID];        // W_e transposed: [d][k], fp16
__device__ float  g_logits[NROWS];      // laid out [s][b] (row r = s*32+b)

#define LDSM4(R0,R1,R2,R3,ADDR) \
  asm volatile("ldmatrix.sync.aligned.m8n8.x4.shared.b16 {%0,%1,%2,%3}, [%4];" \
    : "=r"(R0),"=r"(R1),"=r"(R2),"=r"(R3) : "r"(ADDR))

#define MMA16816(C0,C1,C2,C3,A0,A1,A2,A3,B0,B1) \
  asm volatile("mma.sync.aligned.m16n8k16.row.col.f32.f16.f16.f32 " \
    "{%0,%1,%2,%3},{%4,%5,%6,%7},{%8,%9},{%0,%1,%2,%3};" \
    : "+f"(C0),"+f"(C1),"+f"(C2),"+f"(C3) \
    : "r"(A0),"r"(A1),"r"(A2),"r"(A3),"r"(B0),"r"(B1))

// ---------------------------------------------------------------------------
// k_convW: W_e (rows DHID..DHID+511 of W_attn, [k][d]) -> g_We fp16 [d][k]
// ---------------------------------------------------------------------------
__global__ void k_convW(const float* __restrict__ W)
{
    __shared__ __half tile[32][33];
    int db = blockIdx.x*32, kb = blockIdx.y*32;
    int tx = threadIdx.x, ty = threadIdx.y;     // (32, 8)
    #pragma unroll
    for (int r = 0; r < 4; r++) {
        int kk = ty*4 + r;
        tile[kk][tx] = __float2half(W[(size_t)(DHID + kb + kk)*HID + db + tx]);
    }
    __syncthreads();
    #pragma unroll
    for (int r = 0; r < 4; r++) {
        int dd = ty*4 + r;
        g_We[(size_t)(db + dd)*HID + kb + tx] = tile[tx][dd];
    }
}

// ---------------------------------------------------------------------------
// k_initHP: g_hp[b][d] = b_attn[d]
// ---------------------------------------------------------------------------
__global__ void k_initHP(const float* __restrict__ b_attn)
{
    g_hp[blockIdx.x*HID + threadIdx.x] = b_attn[threadIdx.x];
}

// ---------------------------------------------------------------------------
// k_hpart: g_hp[b][d] += sum_k hidden[b][k] * W_attn[k][d]   (k-split atomics)
// grid (16 k-slices, 4 d-groups), 128 threads
// ---------------------------------------------------------------------------
__global__ void k_hpart(const float* __restrict__ hidden,
                        const float* __restrict__ W)
{
    __shared__ float hs[NBAT][128];
    int ks  = blockIdx.x;            // 0..15
    int dg  = blockIdx.y;            // 0..3
    int tid = threadIdx.x;           // 0..127
    int d   = dg*128 + tid;
    int k0  = ks*128;

    for (int i = tid; i < NBAT*128; i += 128) {
        int b = i >> 7, kk = i & 127;
        hs[b][kk] = hidden[b*DHID + k0 + kk];
    }
    __syncthreads();

    float acc[NBAT];
    #pragma unroll
    for (int b = 0; b < NBAT; b++) acc[b] = 0.f;

    for (int kk = 0; kk < 128; kk++) {
        float w = W[(size_t)(k0 + kk)*HID + d];
        #pragma unroll
        for (int b = 0; b < NBAT; b++) acc[b] = fmaf(hs[b][kk], w, acc[b]);
    }
    #pragma unroll
    for (int b = 0; b < NBAT; b++) atomicAdd(&g_hp[b*HID + d], acc[b]);
}

// ---------------------------------------------------------------------------
// k_main: fused  logits[r] = sum_d tanh( (enc@We)[r,d] + hp[r%32,d] ) * v[d]
// grid 512 CTAs x 256 threads; 8 warps in 4(M) x 2(N) layout, warp tile 32x32
// ---------------------------------------------------------------------------
__global__ void __launch_bounds__(256, 1)
k_main(const float* __restrict__ enc, const float* __restrict__ v)
{
    extern __shared__ char sm[];
    __half* As     = (__half*)(sm);
    __half* Bs     = (__half*)(sm + BS_OFF);
    float*  hps    = (float*) (sm + HP_OFF);   // [32][65]
    float*  vs     = (float*) (sm + VS_OFF);   // [64]
    float*  rowsum = (float*) (sm + RS_OFF);   // [128]

    int tid  = threadIdx.x;
    int warp = tid >> 5, lane = tid & 31;
    int wm   = warp >> 1, wn = warp & 1;
    int g    = lane >> 2, t  = lane & 3;
    int tile0 = blockIdx.x * TM;

    if (tid < TM) rowsum[tid] = 0.f;

    // ---- stage A tile (128 x 512 fp32 -> fp16 smem) ----
    {
        const float4* encv = (const float4*)(enc + (size_t)tile0 * HID);
        #pragma unroll
        for (int i = 0; i < 64; i++) {
            int idx = tid + i*256;
            int r = idx >> 7, c4 = idx & 127;
            float4 f = encv[r*128 + c4];
            __half2* dst = (__half2*)&As[r*LDA + c4*4];
            dst[0] = __floats2half2_rn(f.x, f.y);
            dst[1] = __floats2half2_rn(f.z, f.w);
        }
    }
    __syncthreads();

    uint32_t As_u = (uint32_t)__cvta_generic_to_shared(As);
    uint32_t Bs_u = (uint32_t)__cvta_generic_to_shared(Bs);
    // A fragment ldmatrix addresses (per mt): rows wm*32+mt*16+(lane&15), col (lane>>4)*8
    uint32_t aoff0 = As_u + 2u*((uint32_t)(wm*32 + (lane & 15))*LDA + (((uint32_t)lane >> 4) << 3));
    uint32_t aoff1 = aoff0 + 2u*16u*LDA;
    // B fragment ldmatrix addresses (per nt pair): rows wn*32+p*16+(lane&7)+((lane>>4)*8)
    uint32_t boff0 = Bs_u + 2u*((uint32_t)(wn*32 + (lane & 7) + (((uint32_t)lane >> 4) << 3))*LDB
                              + ((((uint32_t)lane >> 3) & 1) << 3));
    uint32_t boff1 = boff0 + 2u*16u*LDB;

    float part[4] = {0.f, 0.f, 0.f, 0.f};

    for (int nc = 0; nc < 8; nc++) {
        int n0 = nc * NCH;
        if (nc) __syncthreads();   // previous chunk's mma/epilogue done before overwrite

        // ---- load B chunk: 64 n-rows x 512 k halfs (already fp16, k-contig) ----
        {
            const uint4* src = (const uint4*)g_We;
            #pragma unroll
            for (int i = 0; i < 16; i++) {
                int idx = tid + i*256;           // 4096 uint4
                int r = idx >> 6, c = idx & 63;
                uint4 val = src[(size_t)(n0 + r)*64 + c];
                *(uint4*)&Bs[r*LDB + c*8] = val;
            }
        }
        // ---- load hp chunk [32][64] and v chunk ----
        #pragma unroll
        for (int i = 0; i < 8; i++) {
            int idx = tid + i*256;               // 2048
            int b = idx >> 6, c = idx & 63;
            hps[b*65 + c] = g_hp[b*HID + n0 + c];
        }
        if (tid < 64) vs[tid] = v[n0 + tid];
        __syncthreads();

        // ---- mainloop: K = 512, 32 k-steps of 16 ----
        float acc[2][4][4];
        #pragma unroll
        for (int mt = 0; mt < 2; mt++)
            #pragma unroll
            for (int nt = 0; nt < 4; nt++)
                #pragma unroll
                for (int j = 0; j < 4; j++) acc[mt][nt][j] = 0.f;

        #pragma unroll 4
        for (int ks = 0; ks < 32; ks++) {
            uint32_t kb = (uint32_t)ks * 32u;    // bytes = 16 halfs
            uint32_t a0,a1,a2,a3,a4,a5,a6,a7;
            uint32_t b0,b1,b2,b3,b4,b5,b6,b7;
            LDSM4(a0,a1,a2,a3, aoff0 + kb);
            LDSM4(a4,a5,a6,a7, aoff1 + kb);
            LDSM4(b0,b1,b2,b3, boff0 + kb);
            LDSM4(b4,b5,b6,b7, boff1 + kb);
            MMA16816(acc[0][0][0],acc[0][0][1],acc[0][0][2],acc[0][0][3], a0,a1,a2,a3, b0,b1);
            MMA16816(acc[0][1][0],acc[0][1][1],acc[0][1][2],acc[0][1][3], a0,a1,a2,a3, b2,b3);
            MMA16816(acc[0][2][0],acc[0][2][1],acc[0][2][2],acc[0][2][3], a0,a1,a2,a3, b4,b5);
            MMA16816(acc[0][3][0],acc[0][3][1],acc[0][3][2],acc[0][3][3], a0,a1,a2,a3, b6,b7);
            MMA16816(acc[1][0][0],acc[1][0][1],acc[1][0][2],acc[1][0][3], a4,a5,a6,a7, b0,b1);
            MMA16816(acc[1][1][0],acc[1][1][1],acc[1][1][2],acc[1][1][3], a4,a5,a6,a7, b2,b3);
            MMA16816(acc[1][2][0],acc[1][2][1],acc[1][2][2],acc[1][2][3], a4,a5,a6,a7, b4,b5);
            MMA16816(acc[1][3][0],acc[1][3][1],acc[1][3][2],acc[1][3][3], a4,a5,a6,a7, b6,b7);
        }

        // ---- epilogue: tanh(e + hp) * v, accumulate per-row partials ----
        #pragma unroll
        for (int mt = 0; mt < 2; mt++) {
            #pragma unroll
            for (int rh = 0; rh < 2; rh++) {
                int row = wm*32 + mt*16 + rh*8 + g;
                int b   = row & 31;
                float p = 0.f;
                #pragma unroll
                for (int nt = 0; nt < 4; nt++) {
                    #pragma unroll
                    for (int cc = 0; cc < 2; cc++) {
                        int col = wn*32 + nt*8 + 2*t + cc;
                        float x  = acc[mt][nt][rh*2 + cc] + hps[b*65 + col];
                        float e  = __expf(2.f * x);
                        float th = 1.f - __fdividef(2.f, e + 1.f);
                        p = fmaf(th, vs[col], p);
                    }
                }
                part[mt*2 + rh] += p;
            }
        }
    }

    // ---- reduce partials across t-lanes and the 2 wn-warps ----
    #pragma unroll
    for (int i = 0; i < 4; i++) {
        float p = part[i];
        p += __shfl_xor_sync(0xffffffffu, p, 1);
        p += __shfl_xor_sync(0xffffffffu, p, 2);
        if (t == 0) {
            int mt = i >> 1, rh = i & 1;
            int row = wm*32 + mt*16 + rh*8 + g;
            atomicAdd(&rowsum[row], p);
        }
    }
    __syncthreads();
    if (tid < TM) g_logits[tile0 + tid] = rowsum[tid];
}

// ---------------------------------------------------------------------------
// k_softmax: per batch b, softmax over s of g_logits[s*32+b] -> out[b][s]
// ---------------------------------------------------------------------------
__global__ void k_softmax(float* __restrict__ out)
{
    __shared__ float red[8];
    int b = blockIdx.x, tid = threadIdx.x;
    int warp = tid >> 5, lane = tid & 31;

    float x[8];
    #pragma unroll
    for (int j = 0; j < 8; j++) x[j] = g_logits[(j*256 + tid)*NBAT + b];

    float m = x[0];
    #pragma unroll
    for (int j = 1; j < 8; j++) m = fmaxf(m, x[j]);
    #pragma unroll
    for (int o = 16; o; o >>= 1) m = fmaxf(m, __shfl_xor_sync(0xffffffffu, m, o));
    if (lane == 0) red[warp] = m;
    __syncthreads();
    #pragma unroll
    for (int w = 0; w < 8; w++) m = fmaxf(m, red[w]);
    __syncthreads();

    float e[8]; float s = 0.f;
    #pragma unroll
    for (int j = 0; j < 8; j++) { e[j] = expf(x[j] - m); s += e[j]; }
    #pragma unroll
    for (int o = 16; o; o >>= 1) s += __shfl_xor_sync(0xffffffffu, s, o);
    if (lane == 0) red[warp] = s;
    __syncthreads();
    s = 0.f;
    #pragma unroll
    for (int w = 0; w < 8; w++) s += red[w];

    float inv = 1.f / s;
    #pragma unroll
    for (int j = 0; j < 8; j++) out[b*NSEQ + j*256 + tid] = e[j] * inv;
}

// ---------------------------------------------------------------------------
extern "C" void kernel_launch(void* const* d_in, const int* in_sizes, int n_in,
                              void* d_out, int out_size)
{
    const float* hidden = (const float*)d_in[0];   // (32, 2048)
    const float* enc    = (const float*)d_in[1];   // (2048, 32, 512)
    const float* W      = (const float*)d_in[2];   // (2560, 512)
    const float* b_attn = (const float*)d_in[3];   // (512,)
    const float* v      = (const float*)d_in[4];   // (512,)
    float* out = (float*)d_out;                    // (32, 2048)

    cudaFuncSetAttribute(k_main, cudaFuncAttributeMaxDynamicSharedMemorySize, SMEM_TOTAL);

    k_convW <<<dim3(16,16), dim3(32,8)>>>(W);
    k_initHP<<<32, 512>>>(b_attn);
    k_hpart <<<dim3(16,4), 128>>>(hidden, W);
    k_main  <<<NROWS/TM, 256, SMEM_TOTAL>>>(enc, v);
    k_softmax<<<NBAT, 256>>>(out);
}

// round 5
// speedup vs baseline: 1.0496x; 1.0496x over previous
#include <cuda_runtime.h>
#include <cuda_fp16.h>
#include <cstdint>

#define HID   512
#define DHID  2048
#define NBAT  32
#define NSEQ  2048
#define NROWS (NSEQ*NBAT)   // 65536

#define TM    128           // rows per CTA
#define KC    64            // k-chunk width (halfs)
#define NCH   128           // n-chunk width
#define LDT   144           // smem tile row stride in bytes (72 halfs) -> conflict-free ldmatrix
#define TILE_BYTES (128*LDT)   // 18432 per buffer

// ---- SMEM layout (bytes) ----
#define A0_OFF 0
#define A1_OFF 18432
#define B0_OFF 36864
#define B1_OFF 55296
#define VS_OFF 73728            // 512 floats
#define RS_OFF 75776            // 128 floats rowsum
#define SMEM_TOTAL 76288

__device__ float  g_hp[NBAT*HID];
__device__ __half g_We[HID*HID];          // W_e transposed: [n][k] fp16
__device__ __half g_enc16[(size_t)NROWS*HID];  // enc pre-converted to fp16, row-major [row][k]
__device__ float  g_logT[NBAT*NSEQ];      // logits transposed: [b][s]

#define LDSM4(R0,R1,R2,R3,ADDR) \
  asm volatile("ldmatrix.sync.aligned.m8n8.x4.shared.b16 {%0,%1,%2,%3}, [%4];" \
    : "=r"(R0),"=r"(R1),"=r"(R2),"=r"(R3) : "r"(ADDR))

#define MMA16816(C0,C1,C2,C3,A0,A1,A2,A3,B0,B1) \
  asm volatile("mma.sync.aligned.m16n8k16.row.col.f32.f16.f16.f32 " \
    "{%0,%1,%2,%3},{%4,%5,%6,%7},{%8,%9},{%0,%1,%2,%3};" \
    : "+f"(C0),"+f"(C1),"+f"(C2),"+f"(C3) \
    : "r"(A0),"r"(A1),"r"(A2),"r"(A3),"r"(B0),"r"(B1))

#define CP16(DST, SRC) \
  asm volatile("cp.async.cg.shared.global [%0], [%1], 16;" :: "r"(DST), "l"(SRC) : "memory")
#define CP_COMMIT() asm volatile("cp.async.commit_group;" ::: "memory")
#define CP_WAIT1()  asm volatile("cp.async.wait_group 1;" ::: "memory")
#define CP_WAIT0()  asm volatile("cp.async.wait_group 0;" ::: "memory")

__device__ __forceinline__ uint32_t smem_u32(const void* p) {
    uint32_t a;
    asm("{ .reg .u64 t; cvta.to.shared.u64 t, %1; cvt.u32.u64 %0, t; }" : "=r"(a) : "l"(p));
    return a;
}
__device__ __forceinline__ float tanh_approx(float x) {
    float y;
    asm("tanh.approx.f32 %0, %1;" : "=f"(y) : "f"(x));
    return y;
}

// ---------------------------------------------------------------------------
// k_convA: enc fp32 -> g_enc16 fp16 (streaming, coalesced)
// ---------------------------------------------------------------------------
__global__ void k_convA(const float* __restrict__ enc)
{
    const float4* src = (const float4*)enc;
    size_t base = (size_t)blockIdx.x * 1024 + threadIdx.x;
    #pragma unroll
    for (int i = 0; i < 4; i++) {
        size_t idx = base + (size_t)i * 256;      // float4 index, total 8388608
        float4 f = src[idx];
        __half2 h0 = __floats2half2_rn(f.x, f.y);
        __half2 h1 = __floats2half2_rn(f.z, f.w);
        uint2 val;
        val.x = *(uint32_t*)&h0; val.y = *(uint32_t*)&h1;
        *(uint2*)(g_enc16 + idx*4) = val;
    }
}

// ---------------------------------------------------------------------------
// k_convW: W_e (rows DHID.. of W_attn, [k][d]) -> g_We fp16 [n][k], coalesced
// grid (8 kc-of-64, 16 nb-of-32), 256 threads
// ---------------------------------------------------------------------------
__global__ void k_convW(const float* __restrict__ W)
{
    __shared__ float t[64][33];
    int kc = blockIdx.x, n0 = blockIdx.y * 32;
    int tid = threadIdx.x;
    #pragma unroll
    for (int i = 0; i < 8; i++) {
        int r = (tid >> 5) + i * 8;      // kin 0..63
        int c = tid & 31;                // n_local
        t[r][c] = W[(size_t)(DHID + kc*64 + r)*HID + n0 + c];
    }
    __syncthreads();
    int nl = tid >> 3;                   // 0..31
    int g  = tid & 7;                    // group of 8 k's
    int n  = n0 + nl;
    __half2 h0 = __floats2half2_rn(t[g*8+0][nl], t[g*8+1][nl]);
    __half2 h1 = __floats2half2_rn(t[g*8+2][nl], t[g*8+3][nl]);
    __half2 h2 = __floats2half2_rn(t[g*8+4][nl], t[g*8+5][nl]);
    __half2 h3 = __floats2half2_rn(t[g*8+6][nl], t[g*8+7][nl]);
    uint4 val;
    val.x = *(uint32_t*)&h0; val.y = *(uint32_t*)&h1;
    val.z = *(uint32_t*)&h2; val.w = *(uint32_t*)&h3;
    *(uint4*)(g_We + (size_t)n*HID + kc*64 + g*8) = val;
}

// ---------------------------------------------------------------------------
__global__ void k_initHP(const float* __restrict__ b_attn)
{
    g_hp[blockIdx.x*HID + threadIdx.x] = b_attn[threadIdx.x];
}

__global__ void k_hpart(const float* __restrict__ hidden,
                        const float* __restrict__ W)
{
    __shared__ float hs[NBAT][128];
    int ks  = blockIdx.x;            // 0..15
    int dg  = blockIdx.y;            // 0..3
    int tid = threadIdx.x;           // 0..127
    int d   = dg*128 + tid;
    int k0  = ks*128;

    for (int i = tid; i < NBAT*128; i += 128) {
        int b = i >> 7, kk = i & 127;
        hs[b][kk] = hidden[b*DHID + k0 + kk];
    }
    __syncthreads();

    float acc[NBAT];
    #pragma unroll
    for (int b = 0; b < NBAT; b++) acc[b] = 0.f;

    for (int kk = 0; kk < 128; kk++) {
        float w = W[(size_t)(k0 + kk)*HID + d];
        #pragma unroll
        for (int b = 0; b < NBAT; b++) acc[b] = fmaf(hs[b][kk], w, acc[b]);
    }
    #pragma unroll
    for (int b = 0; b < NBAT; b++) atomicAdd(&g_hp[b*HID + d], acc[b]);
}

// ---------------------------------------------------------------------------
// k_main v3: double-buffered cp.async GEMM, warp tile 64x32, 2 CTAs/SM.
// 512 CTAs x 256 threads. Warp grid 2(M) x 4(N). CTA tile 128 x 128 per n-chunk.
// 32 global chunks gi = nc*8 + kc; epilogue fused at kc==7.
// ---------------------------------------------------------------------------
__device__ __forceinline__ void prefetch_chunk(uint32_t abuf, uint32_t bbuf,
                                               const __half* __restrict__ encrow,
                                               int nc, int kc, int tid)
{
    #pragma unroll
    for (int i = 0; i < 4; i++) {
        int idx = tid + i*256;               // 0..1023
        int m   = idx >> 3, seg = idx & 7;
        CP16(abuf + m*LDT + seg*16, encrow + (size_t)m*HID + kc*KC + seg*8);
    }
    #pragma unroll
    for (int i = 0; i < 4; i++) {
        int idx = tid + i*256;
        int n   = idx >> 3, seg = idx & 7;
        CP16(bbuf + n*LDT + seg*16, g_We + (size_t)(nc*NCH + n)*HID + kc*KC + seg*8);
    }
    CP_COMMIT();
}

__global__ void __launch_bounds__(256, 2)
k_main(const float* __restrict__ v)
{
    extern __shared__ char sm[];
    const uint32_t smem_base = smem_u32(sm);
    const int tid  = threadIdx.x;
    const int warp = tid >> 5, lane = tid & 31;
    const int wm   = warp >> 2, wn = warp & 3;
    const int g    = lane >> 2, t = lane & 3;
    const int tile0 = blockIdx.x * TM;

    float* vs = (float*)(sm + VS_OFF);
    float* rowsum = (float*)(sm + RS_OFF);

    vs[tid] = v[tid];
    vs[tid + 256] = v[tid + 256];
    if (tid < TM) rowsum[tid] = 0.f;

    const __half* encrow = g_enc16 + (size_t)tile0 * HID;

    // lane-dependent ldmatrix offsets
    const uint32_t arow_off = (uint32_t)(lane & 15)*LDT + ((uint32_t)lane >> 4)*16
                            + (uint32_t)wm*64*LDT;
    const uint32_t brow_off = ((uint32_t)(lane & 7) + (((uint32_t)lane >> 4) << 3))*LDT
                            + ((((uint32_t)lane >> 3) & 1) << 4)
                            + (uint32_t)wn*32*LDT;

    float acc[4][4][4];
    #pragma unroll
    for (int mt = 0; mt < 4; mt++)
        #pragma unroll
        for (int nt = 0; nt < 4; nt++)
            #pragma unroll
            for (int j = 0; j < 4; j++) acc[mt][nt][j] = 0.f;

    prefetch_chunk(smem_base + A0_OFF, smem_base + B0_OFF, encrow, 0, 0, tid);
    prefetch_chunk(smem_base + A1_OFF, smem_base + B1_OFF, encrow, 0, 1, tid);

    #pragma unroll 1
    for (int gi = 0; gi < 32; gi++) {
        const int s = gi & 1;
        if (gi == 31) { CP_WAIT0(); } else { CP_WAIT1(); }
        __syncthreads();

        const uint32_t Ab = smem_base + (s ? A1_OFF : A0_OFF) + arow_off;
        const uint32_t Bb = smem_base + (s ? B1_OFF : B0_OFF) + brow_off;

        #pragma unroll
        for (int ks = 0; ks < 4; ks++) {
            uint32_t A[4][4], B[2][4];
            #pragma unroll
            for (int mt = 0; mt < 4; mt++)
                LDSM4(A[mt][0], A[mt][1], A[mt][2], A[mt][3], Ab + mt*16*LDT + ks*32);
            #pragma unroll
            for (int p = 0; p < 2; p++)
                LDSM4(B[p][0], B[p][1], B[p][2], B[p][3], Bb + p*16*LDT + ks*32);
            #pragma unroll
            for (int mt = 0; mt < 4; mt++) {
                #pragma unroll
                for (int nt = 0; nt < 4; nt++) {
                    const int p = nt >> 1, h = (nt & 1) << 1;
                    MMA16816(acc[mt][nt][0], acc[mt][nt][1], acc[mt][nt][2], acc[mt][nt][3],
                             A[mt][0], A[mt][1], A[mt][2], A[mt][3],
                             B[p][h], B[p][h+1]);
                }
            }
        }
        __syncthreads();

        if (gi + 2 < 32) {
            const int gi2 = gi + 2;
            prefetch_chunk(smem_base + (s ? A1_OFF : A0_OFF),
                           smem_base + (s ? B1_OFF : B0_OFF),
                           encrow, gi2 >> 3, gi2 & 7, tid);
        }

        if ((gi & 7) == 7) {
            // ---- epilogue for n-chunk nc = gi>>3 ----
            const int nc = gi >> 3;
            #pragma unroll
            for (int mt = 0; mt < 4; mt++) {
                #pragma unroll
                for (int rh = 0; rh < 2; rh++) {
                    const int row = wm*64 + mt*16 + rh*8 + g;
                    const int b   = row & 31;
                    float p = 0.f;
                    #pragma unroll
                    for (int nt = 0; nt < 4; nt++) {
                        const int col = nc*NCH + wn*32 + nt*8 + t*2;
                        float2 hp2 = __ldg((const float2*)(g_hp + b*HID + col));
                        const float2 v2 = *(const float2*)(vs + col);
                        float x0 = tanh_approx(acc[mt][nt][rh*2 + 0] + hp2.x);
                        float x1 = tanh_approx(acc[mt][nt][rh*2 + 1] + hp2.y);
                        p = fmaf(x0, v2.x, p);
                        p = fmaf(x1, v2.y, p);
                        acc[mt][nt][rh*2 + 0] = 0.f;
                        acc[mt][nt][rh*2 + 1] = 0.f;
                    }
                    p += __shfl_xor_sync(0xffffffffu, p, 1);
                    p += __shfl_xor_sync(0xffffffffu, p, 2);
                    if (t == 0) atomicAdd(&rowsum[row], p);
                }
            }
        }
    }

    __syncthreads();
    if (tid < TM) {
        const int r = tile0 + tid;
        g_logT[(r & 31)*NSEQ + (r >> 5)] = rowsum[tid];
    }
}

// ---------------------------------------------------------------------------
// k_softmax: per batch b, softmax over s of g_logT[b][s] -> out[b][s] (coalesced)
// ---------------------------------------------------------------------------
__global__ void k_softmax(float* __restrict__ out)
{
    __shared__ float red[8];
    int b = blockIdx.x, tid = threadIdx.x;
    int warp = tid >> 5, lane = tid & 31;

    float x[8];
    #pragma unroll
    for (int j = 0; j < 8; j++) x[j] = g_logT[b*NSEQ + j*256 + tid];

    float m = x[0];
    #pragma unroll
    for (int j = 1; j < 8; j++) m = fmaxf(m, x[j]);
    #pragma unroll
    for (int o = 16; o; o >>= 1) m = fmaxf(m, __shfl_xor_sync(0xffffffffu, m, o));
    if (lane == 0) red[warp] = m;
    __syncthreads();
    #pragma unroll
    for (int w = 0; w < 8; w++) m = fmaxf(m, red[w]);
    __syncthreads();

    float e[8]; float s = 0.f;
    #pragma unroll
    for (int j = 0; j < 8; j++) { e[j] = expf(x[j] - m); s += e[j]; }
    #pragma unroll
    for (int o = 16; o; o >>= 1) s += __shfl_xor_sync(0xffffffffu, s, o);
    if (lane == 0) red[warp] = s;
    __syncthreads();
    s = 0.f;
    #pragma unroll
    for (int w = 0; w < 8; w++) s += red[w];

    float inv = 1.f / s;
    #pragma unroll
    for (int j = 0; j < 8; j++) out[b*NSEQ + j*256 + tid] = e[j] * inv;
}

// ---------------------------------------------------------------------------
extern "C" void kernel_launch(void* const* d_in, const int* in_sizes, int n_in,
                              void* d_out, int out_size)
{
    const float* hidden = (const float*)d_in[0];   // (32, 2048)
    const float* enc    = (const float*)d_in[1];   // (2048, 32, 512)
    const float* W      = (const float*)d_in[2];   // (2560, 512)
    const float* b_attn = (const float*)d_in[3];   // (512,)
    const float* v      = (const float*)d_in[4];   // (512,)
    float* out = (float*)d_out;                    // (32, 2048)

    cudaFuncSetAttribute(k_main, cudaFuncAttributeMaxDynamicSharedMemorySize, SMEM_TOTAL);

    k_convA  <<<8192, 256>>>(enc);
    k_convW  <<<dim3(8,16), 256>>>(W);
    k_initHP <<<32, 512>>>(b_attn);
    k_hpart  <<<dim3(16,4), 128>>>(hidden, W);
    k_main   <<<NROWS/TM, 256, SMEM_TOTAL>>>(v);
    k_softmax<<<NBAT, 256>>>(out);
}

// round 12
// speedup vs baseline: 1.2883x; 1.2274x over previous
#include <cuda_runtime.h>
#include <cuda_fp16.h>
#include <cstdint>

#define HID   512
#define DHID  2048
#define NBAT  32
#define NSEQ  2048
#define NROWS (NSEQ*NBAT)   // 65536

#define TM    128           // rows per CTA
#define KC    64            // k-chunk width (halfs)
#define NCH   128           // n-chunk width
#define LDT   144           // smem tile row stride in bytes (72 halfs) -> conflict-free ldmatrix
#define TILE_BYTES (128*LDT)   // 18432 per buffer

// ---- SMEM layout (bytes): 3-stage A + 3-stage B ----
#define B_BASE  (3*TILE_BYTES)      // 55296
#define VS_OFF  (6*TILE_BYTES)      // 110592 (512 floats)
#define RS_OFF  (VS_OFF + 2048)     // 112640 (128 floats)
#define SMEM_TOTAL (RS_OFF + 512)   // 113152

// ---- heterogeneous prep grid: small jobs FIRST so they overlap convA ----
#define HP_BLKS    128
#define CONVW_BLKS 128
#define CONVA_BLKS 8192
#define PREP_BLKS  (HP_BLKS + CONVW_BLKS + CONVA_BLKS)

__device__ float  g_hp[NBAT*HID];
__device__ __half g_We[HID*HID];               // W_e transposed: [n][k] fp16
__device__ __half g_enc16[(size_t)NROWS*HID];  // enc fp16, row-major [row][k]
__device__ float  g_logT[NBAT*NSEQ];           // logits transposed: [b][s]

#define LDSM4(R0,R1,R2,R3,ADDR) \
  asm volatile("ldmatrix.sync.aligned.m8n8.x4.shared.b16 {%0,%1,%2,%3}, [%4];" \
    : "=r"(R0),"=r"(R1),"=r"(R2),"=r"(R3) : "r"(ADDR))

#define MMA16816(C0,C1,C2,C3,A0,A1,A2,A3,B0,B1) \
  asm volatile("mma.sync.aligned.m16n8k16.row.col.f32.f16.f16.f32 " \
    "{%0,%1,%2,%3},{%4,%5,%6,%7},{%8,%9},{%0,%1,%2,%3};" \
    : "+f"(C0),"+f"(C1),"+f"(C2),"+f"(C3) \
    : "r"(A0),"r"(A1),"r"(A2),"r"(A3),"r"(B0),"r"(B1))

#define CP16(DST, SRC) \
  asm volatile("cp.async.cg.shared.global [%0], [%1], 16;" :: "r"(DST), "l"(SRC) : "memory")
#define CP_COMMIT() asm volatile("cp.async.commit_group;" ::: "memory")
#define CP_WAIT1()  asm volatile("cp.async.wait_group 1;" ::: "memory")
#define CP_WAIT0()  asm volatile("cp.async.wait_group 0;" ::: "memory")

__device__ __forceinline__ uint32_t smem_u32(const void* p) {
    uint32_t a;
    asm("{ .reg .u64 t; cvta.to.shared.u64 t, %1; cvt.u32.u64 %0, t; }" : "=r"(a) : "l"(p));
    return a;
}
__device__ __forceinline__ float tanh_approx(float x) {
    float y;
    asm("tanh.approx.f32 %0, %1;" : "=f"(y) : "f"(x));
    return y;
}

// ---------------------------------------------------------------------------
// k_initHP: g_hp[b][d] = b_attn[d]   (must precede k_prep's hpart atomics)
// ---------------------------------------------------------------------------
__global__ void k_initHP(const float* __restrict__ b_attn)
{
    g_hp[blockIdx.x*HID + threadIdx.x] = b_attn[threadIdx.x];
}

// ---------------------------------------------------------------------------
// k_prep: heterogeneous grid, 256 threads/block.
//  [0, 128):      hpart  — g_hp += hidden @ W_h  (k-split, batch-split)
//  [128, 256):    convW  — W_e -> g_We fp16 [n][k]
//  [256, 8448):   convA  — enc fp32 -> g_enc16 fp16 (streaming)
// Small jobs first: they run in wave 1 and hide under convA's memory time.
// ---------------------------------------------------------------------------
__global__ void __launch_bounds__(256)
k_prep(const float* __restrict__ enc, const float* __restrict__ W,
       const float* __restrict__ hidden)
{
    __shared__ float sh[64*33];          // convW transpose tile / hpart hs[8][128]
    const int p = blockIdx.x;
    const int tid = threadIdx.x;

    if (p < HP_BLKS) {
        // ---------------- hpart: 16 ks x 2 dg x 4 bg ----------------
        const int ks = p & 15;
        const int dg = (p >> 4) & 1;
        const int bg = p >> 5;
        const int d  = dg*256 + tid;
        const int k0 = ks*128;
        const int b0 = bg*8;

        #pragma unroll
        for (int i = tid; i < 8*128; i += 256) {
            int b = i >> 7, kk = i & 127;
            sh[b*128 + kk] = hidden[(size_t)(b0 + b)*DHID + k0 + kk];
        }
        __syncthreads();

        float acc[8];
        #pragma unroll
        for (int b = 0; b < 8; b++) acc[b] = 0.f;

        #pragma unroll 4
        for (int kk = 0; kk < 128; kk++) {
            float w = W[(size_t)(k0 + kk)*HID + d];
            #pragma unroll
            for (int b = 0; b < 8; b++) acc[b] = fmaf(sh[b*128 + kk], w, acc[b]);
        }
        #pragma unroll
        for (int b = 0; b < 8; b++) atomicAdd(&g_hp[(b0 + b)*HID + d], acc[b]);
    }
    else if (p < HP_BLKS + CONVW_BLKS) {
        // ---------------- convW: 8 kc x 16 nb ----------------
        const int q  = p - HP_BLKS;
        const int kc = q & 7;
        const int n0 = (q >> 3) * 32;
        const int tx = tid & 31, ty = tid >> 5;
        #pragma unroll
        for (int i = 0; i < 8; i++) {
            int r = ty + i * 8;              // kin 0..63
            sh[r*33 + tx] = W[(size_t)(DHID + kc*64 + r)*HID + n0 + tx];
        }
        __syncthreads();
        int nl = tid >> 3;                   // 0..31
        int g  = tid & 7;                    // group of 8 k's
        int n  = n0 + nl;
        __half2 h0 = __floats2half2_rn(sh[(g*8+0)*33 + nl], sh[(g*8+1)*33 + nl]);
        __half2 h1 = __floats2half2_rn(sh[(g*8+2)*33 + nl], sh[(g*8+3)*33 + nl]);
        __half2 h2 = __floats2half2_rn(sh[(g*8+4)*33 + nl], sh[(g*8+5)*33 + nl]);
        __half2 h3 = __floats2half2_rn(sh[(g*8+6)*33 + nl], sh[(g*8+7)*33 + nl]);
        uint4 val;
        val.x = *(uint32_t*)&h0; val.y = *(uint32_t*)&h1;
        val.z = *(uint32_t*)&h2; val.w = *(uint32_t*)&h3;
        *(uint4*)(g_We + (size_t)n*HID + kc*64 + g*8) = val;
    }
    else {
        // ---------------- convA ----------------
        const int q = p - (HP_BLKS + CONVW_BLKS);
        const float4* src = (const float4*)enc;
        size_t base = (size_t)q * 1024 + tid;
        #pragma unroll
        for (int i = 0; i < 4; i++) {
            size_t idx = base + (size_t)i * 256;
            float4 f = src[idx];
            __half2 h0 = __floats2half2_rn(f.x, f.y);
            __half2 h1 = __floats2half2_rn(f.z, f.w);
            uint2 val;
            val.x = *(uint32_t*)&h0; val.y = *(uint32_t*)&h1;
            *(uint2*)(g_enc16 + idx*4) = val;
        }
    }
}

// ---------------------------------------------------------------------------
// k_main v4: triple-buffered cp.async GEMM, one __syncthreads per chunk.
// 512 CTAs x 256 threads, 2 CTAs/SM. Warp grid 2(M) x 4(N), warp tile 64x32.
// 32 chunks gi = nc*8 + kc (4 n-chunks x 8 k-chunks); epilogue at kc==7.
// ---------------------------------------------------------------------------
__device__ __forceinline__ void prefetch_chunk(uint32_t abuf, uint32_t bbuf,
                                               const __half* __restrict__ encrow,
                                               int nc, int kc, int tid)
{
    #pragma unroll
    for (int i = 0; i < 4; i++) {
        int idx = tid + i*256;               // 0..1023
        int m   = idx >> 3, seg = idx & 7;
        CP16(abuf + m*LDT + seg*16, encrow + (size_t)m*HID + kc*KC + seg*8);
    }
    #pragma unroll
    for (int i = 0; i < 4; i++) {
        int idx = tid + i*256;
        int n   = idx >> 3, seg = idx & 7;
        CP16(bbuf + n*LDT + seg*16, g_We + (size_t)(nc*NCH + n)*HID + kc*KC + seg*8);
    }
    CP_COMMIT();
}

__global__ void __launch_bounds__(256, 2)
k_main(const float* __restrict__ v)
{
    extern __shared__ char sm[];
    const uint32_t smem_base = smem_u32(sm);
    const int tid  = threadIdx.x;
    const int warp = tid >> 5, lane = tid & 31;
    const int wm   = warp >> 2, wn = warp & 3;
    const int g    = lane >> 2, t = lane & 3;
    const int tile0 = blockIdx.x * TM;

    float* vs = (float*)(sm + VS_OFF);
    float* rowsum = (float*)(sm + RS_OFF);

    vs[tid] = v[tid];
    vs[tid + 256] = v[tid + 256];
    if (tid < TM) rowsum[tid] = 0.f;

    const __half* encrow = g_enc16 + (size_t)tile0 * HID;

    // lane-dependent ldmatrix offsets
    const uint32_t arow_off = (uint32_t)(lane & 15)*LDT + ((uint32_t)lane >> 4)*16
                            + (uint32_t)wm*64*LDT;
    const uint32_t brow_off = ((uint32_t)(lane & 7) + (((uint32_t)lane >> 4) << 3))*LDT
                            + ((((uint32_t)lane >> 3) & 1) << 4)
                            + (uint32_t)wn*32*LDT;

    float acc[4][4][4];
    #pragma unroll
    for (int mt = 0; mt < 4; mt++)
        #pragma unroll
        for (int nt = 0; nt < 4; nt++)
            #pragma unroll
            for (int j = 0; j < 4; j++) acc[mt][nt][j] = 0.f;

    prefetch_chunk(smem_base + 0*TILE_BYTES, smem_base + B_BASE + 0*TILE_BYTES,
                   encrow, 0, 0, tid);
    prefetch_chunk(smem_base + 1*TILE_BYTES, smem_base + B_BASE + 1*TILE_BYTES,
                   encrow, 0, 1, tid);

    int s = 0, sp = 2;      // compute buffer, prefetch buffer (gi+2)%3
    #pragma unroll 1
    for (int gi = 0; gi < 32; gi++) {
        if (gi == 31) { CP_WAIT0(); } else { CP_WAIT1(); }
        __syncthreads();

        if (gi + 2 < 32) {
            const int gi2 = gi + 2;
            prefetch_chunk(smem_base + sp*TILE_BYTES,
                           smem_base + B_BASE + sp*TILE_BYTES,
                           encrow, gi2 >> 3, gi2 & 7, tid);
        }

        const uint32_t Ab = smem_base + s*TILE_BYTES + arow_off;
        const uint32_t Bb = smem_base + B_BASE + s*TILE_BYTES + brow_off;

        #pragma unroll
        for (int ks = 0; ks < 4; ks++) {
            uint32_t A[4][4], B[2][4];
            #pragma unroll
            for (int mt = 0; mt < 4; mt++)
                LDSM4(A[mt][0], A[mt][1], A[mt][2], A[mt][3], Ab + mt*16*LDT + ks*32);
            #pragma unroll
            for (int p = 0; p < 2; p++)
                LDSM4(B[p][0], B[p][1], B[p][2], B[p][3], Bb + p*16*LDT + ks*32);
            #pragma unroll
            for (int mt = 0; mt < 4; mt++) {
                #pragma unroll
                for (int nt = 0; nt < 4; nt++) {
                    const int p = nt >> 1, h = (nt & 1) << 1;
                    MMA16816(acc[mt][nt][0], acc[mt][nt][1], acc[mt][nt][2], acc[mt][nt][3],
                             A[mt][0], A[mt][1], A[mt][2], A[mt][3],
                             B[p][h], B[p][h+1]);
                }
            }
        }

        if ((gi & 7) == 7) {
            // ---- epilogue for n-chunk nc = gi>>3 ----
            const int nc = gi >> 3;
            #pragma unroll
            for (int mt = 0; mt < 4; mt++) {
                #pragma unroll
                for (int rh = 0; rh < 2; rh++) {
                    const int row = wm*64 + mt*16 + rh*8 + g;
                    const int b   = row & 31;
                    float p = 0.f;
                    #pragma unroll
                    for (int nt = 0; nt < 4; nt++) {
                        const int col = nc*NCH + wn*32 + nt*8 + t*2;
                        float2 hp2 = __ldg((const float2*)(g_hp + b*HID + col));
                        const float2 v2 = *(const float2*)(vs + col);
                        float x0 = tanh_approx(acc[mt][nt][rh*2 + 0] + hp2.x);
                        float x1 = tanh_approx(acc[mt][nt][rh*2 + 1] + hp2.y);
                        p = fmaf(x0, v2.x, p);
                        p = fmaf(x1, v2.y, p);
                        acc[mt][nt][rh*2 + 0] = 0.f;
                        acc[mt][nt][rh*2 + 1] = 0.f;
                    }
                    p += __shfl_xor_sync(0xffffffffu, p, 1);
                    p += __shfl_xor_sync(0xffffffffu, p, 2);
                    if (t == 0) atomicAdd(&rowsum[row], p);
                }
            }
        }

        s  = (s  == 2) ? 0 : s  + 1;
        sp = (sp == 2) ? 0 : sp + 1;
    }

    __syncthreads();
    if (tid < TM) {
        const int r = tile0 + tid;
        g_logT[(r & 31)*NSEQ + (r >> 5)] = rowsum[tid];
    }
}

// ---------------------------------------------------------------------------
// k_softmax: per batch b, softmax over s of g_logT[b][s] -> out[b][s]
// ---------------------------------------------------------------------------
__global__ void k_softmax(float* __restrict__ out)
{
    __shared__ float red[8];
    int b = blockIdx.x, tid = threadIdx.x;
    int warp = tid >> 5, lane = tid & 31;

    float x[8];
    #pragma unroll
    for (int j = 0; j < 8; j++) x[j] = g_logT[b*NSEQ + j*256 + tid];

    float m = x[0];
    #pragma unroll
    for (int j = 1; j < 8; j++) m = fmaxf(m, x[j]);
    #pragma unroll
    for (int o = 16; o; o >>= 1) m = fmaxf(m, __shfl_xor_sync(0xffffffffu, m, o));
    if (lane == 0) red[warp] = m;
    __syncthreads();
    #pragma unroll
    for (int w = 0; w < 8; w++) m = fmaxf(m, red[w]);
    __syncthreads();

    float e[8]; float s = 0.f;
    #pragma unroll
    for (int j = 0; j < 8; j++) { e[j] = expf(x[j] - m); s += e[j]; }
    #pragma unroll
    for (int o = 16; o; o >>= 1) s += __shfl_xor_sync(0xffffffffu, s, o);
    if (lane == 0) red[warp] = s;
    __syncthreads();
    s = 0.f;
    #pragma unroll
    for (int w = 0; w < 8; w++) s += red[w];

    float inv = 1.f / s;
    #pragma unroll
    for (int j = 0; j < 8; j++) out[b*NSEQ + j*256 + tid] = e[j] * inv;
}

// ---------------------------------------------------------------------------
extern "C" void kernel_launch(void* const* d_in, const int* in_sizes, int n_in,
                              void* d_out, int out_size)
{
    const float* hidden = (const float*)d_in[0];   // (32, 2048)
    const float* enc    = (const float*)d_in[1];   // (2048, 32, 512)
    const float* W      = (const float*)d_in[2];   // (2560, 512)
    const float* b_attn = (const float*)d_in[3];   // (512,)
    const float* v      = (const float*)d_in[4];   // (512,)
    float* out = (float*)d_out;                    // (32, 2048)

    cudaFuncSetAttribute(k_main, cudaFuncAttributeMaxDynamicSharedMemorySize, SMEM_TOTAL);

    k_initHP <<<32, 512>>>(b_attn);
    k_prep   <<<PREP_BLKS, 256>>>(enc, W, hidden);
    k_main   <<<NROWS/TM, 256, SMEM_TOTAL>>>(v);
    k_softmax<<<NBAT, 256>>>(out);
}